// round 12
// baseline (speedup 1.0000x reference)
#include <cuda_runtime.h>
#include <cuda_bf16.h>
#include <cstdint>

// Gate_8108898255611 — router gate, single-chain bf16 mma.sync + exact rescore.
//   out[0:T)  = 1.0f (STE forward == one-hot)
//   out[T:2T) = argmax_e <x_t, w_e> as float
// R12: software-pipelined fragments. b double-buffered (ldsm for t+1 issued
// before MMAs of t), a prefetched per k-block; x packed to bf16 at load time
// (xp[4] uint4 = 16 regs vs xv[8] float4 = 32) to pay for the extra buffers.

constexpr int T_TOK = 16384;
constexpr int DIM   = 4096;
constexpr int NEXP  = 256;
constexpr int BM    = 128;            // tokens per CTA
constexpr int KC    = 64;             // k per chunk (128B bf16 rows)
constexpr int NCHUNK = DIM / KC;      // 64
constexpr int NSTAGES = 4;
constexpr int NTHREADS = 256;         // 8 warps, 2x4 grid of 64x64 tiles
constexpr float TAU = 0.02f;

constexpr int A_SZ  = BM * 128;       // 16KB (128 rows x 128B bf16)
constexpr int B_SZ  = NEXP * 128;     // 32KB
constexpr int STAGE = A_SZ + B_SZ;    // 48KB
constexpr int SMEM_TOTAL = NSTAGES * STAGE;   // 192KB
constexpr int SC_STRIDE = 257;

__device__ __nv_bfloat16 g_w_bf[NEXP * DIM];

// ---------------- helpers ----------------
__device__ __forceinline__ uint32_t smem_u32(const void* p) {
    uint32_t a;
    asm("{ .reg .u64 t; cvta.to.shared.u64 t, %1; cvt.u32.u64 %0, t; }"
        : "=r"(a) : "l"(p));
    return a;
}
__device__ __forceinline__ uint32_t sw128(uint32_t off) {
    return off ^ ((off >> 3) & 0x70);
}
__device__ __forceinline__ uint32_t pack_bf2(__nv_bfloat16 a, __nv_bfloat16 b) {
    return (uint32_t)__bfloat16_as_ushort(a) | ((uint32_t)__bfloat16_as_ushort(b) << 16);
}
__device__ __forceinline__ void ldsm4(uint32_t* r, uint32_t addr) {
    asm("ldmatrix.sync.aligned.m8n8.x4.shared.b16 {%0,%1,%2,%3}, [%4];"
        : "=r"(r[0]), "=r"(r[1]), "=r"(r[2]), "=r"(r[3]) : "r"(addr) : "memory");
}
__device__ __forceinline__ void mma_bf16(float* d, const uint32_t* a,
                                         uint32_t b0, uint32_t b1) {
    asm("mma.sync.aligned.m16n8k16.row.col.f32.bf16.bf16.f32 "
        "{%0,%1,%2,%3}, {%4,%5,%6,%7}, {%8,%9}, {%0,%1,%2,%3};"
        : "+f"(d[0]), "+f"(d[1]), "+f"(d[2]), "+f"(d[3])
        : "r"(a[0]), "r"(a[1]), "r"(a[2]), "r"(a[3]), "r"(b0), "r"(b1));
}
__device__ __forceinline__ void cp_async16(uint32_t dst, const void* src) {
    asm volatile("cp.async.cg.shared.global [%0], [%1], 16;"
                 :: "r"(dst), "l"(src) : "memory");
}
__device__ __forceinline__ void cp_commit() {
    asm volatile("cp.async.commit_group;" ::: "memory");
}
__device__ __forceinline__ void cp_wait2() {
    asm volatile("cp.async.wait_group 2;" ::: "memory");
}

// ---------------- w pre-convert (round-nearest bf16) ----------------
__global__ void wconv_kernel(const float* __restrict__ w) {
    int n4 = NEXP * DIM / 4;
    for (int i = blockIdx.x * blockDim.x + threadIdx.x; i < n4;
         i += gridDim.x * blockDim.x) {
        float4 v = reinterpret_cast<const float4*>(w)[i];
        reinterpret_cast<uint2*>(g_w_bf)[i] =
            make_uint2(pack_bf2(__float2bfloat16(v.x), __float2bfloat16(v.y)),
                       pack_bf2(__float2bfloat16(v.z), __float2bfloat16(v.w)));
    }
}

// ---------------- main kernel ----------------
__global__ __launch_bounds__(NTHREADS, 1)
void gate_mma_kernel(const float* __restrict__ x,
                     const float* __restrict__ w,
                     float* __restrict__ out)
{
    extern __shared__ char smem[];
    __shared__ int   s_cnt;
    __shared__ int   s_list[BM];
    __shared__ float s_m1[BM];
    const uint32_t sb = smem_u32(smem);
    const int tid  = threadIdx.x;
    const int lane = tid & 31;
    const int wid  = tid >> 5;
    const int wm   = wid >> 2;   // 0..1 -> 64-row strip
    const int wn   = wid & 3;    // 0..3 -> 64-col strip
    const int t0   = blockIdx.x * BM;
    const float* xbase = x + (size_t)t0 * DIM;

    if (tid == 0) s_cnt = 0;

    float acc[4][8][4];   // 64x64 tile: mi 0..3 (16-row), nj 0..7 (8-col)
#pragma unroll
    for (int i = 0; i < 4; i++)
#pragma unroll
        for (int j = 0; j < 8; j++)
#pragma unroll
            for (int q = 0; q < 4; q++) acc[i][j][q] = 0.f;

    uint4 xp[4];  // prefetched x chunk, already packed bf16 (8 vals/uint4)

    auto load_x = [&](int k0) {
#pragma unroll
        for (int t = 0; t < 4; ++t) {
            const int i = tid + t * NTHREADS;    // 1024 items of 8 floats
            const int r = i >> 3, c8 = (i & 7) << 3;
            const float* src = xbase + (size_t)r * DIM + k0 + c8;
            const float4 va = *reinterpret_cast<const float4*>(src);
            const float4 vb = *reinterpret_cast<const float4*>(src + 4);
            xp[t].x = pack_bf2(__float2bfloat16(va.x), __float2bfloat16(va.y));
            xp[t].y = pack_bf2(__float2bfloat16(va.z), __float2bfloat16(va.w));
            xp[t].z = pack_bf2(__float2bfloat16(vb.x), __float2bfloat16(vb.y));
            xp[t].w = pack_bf2(__float2bfloat16(vb.z), __float2bfloat16(vb.w));
        }
    };
    auto sts_x = [&](int s) {
        char* aB = smem + s * STAGE;
#pragma unroll
        for (int t = 0; t < 4; ++t) {
            const int i = tid + t * NTHREADS;
            const int r = i >> 3, c8 = (i & 7) << 3;
            const uint32_t off = sw128((uint32_t)(r * 128 + c8 * 2));
            *reinterpret_cast<uint4*>(aB + off) = xp[t];
        }
    };
    auto cpasync_w = [&](int s, int k0) {
        const uint32_t bB = sb + s * STAGE + A_SZ;
#pragma unroll
        for (int t = 0; t < 8; ++t) {
            const int i = tid + t * NTHREADS;
            const int r = i >> 3, c16 = (i & 7) << 4;
            const uint32_t off = sw128((uint32_t)(r * 128 + c16));
            const size_t gs = ((size_t)r * DIM + k0) * 2 + c16;
            cp_async16(bB + off, (const char*)g_w_bf + gs);
        }
    };
    auto compute = [&](int s) {
        const uint32_t aB = sb + s * STAGE;
        const uint32_t bB = aB + A_SZ;
        uint32_t a[4][4], b[2][4];
        auto lda = [&](int k) {
#pragma unroll
            for (int mi = 0; mi < 4; ++mi) {
                const int row = wm * 64 + mi * 16 + (lane & 15);
                const int byt = ((lane >> 4) << 4) + k * 32;
                ldsm4(a[mi], aB + sw128((uint32_t)(row * 128 + byt)));
            }
        };
        auto ldb = [&](uint32_t* dst, int k, int t) {
            const int nrow = wn * 64 + t * 16 + (lane & 7) + ((lane >> 4) << 3);
            const int byt  = k * 32 + (((lane >> 3) & 1) << 4);
            ldsm4(dst, bB + sw128((uint32_t)(nrow * 128 + byt)));
        };
        lda(0);
        ldb(b[0], 0, 0);
#pragma unroll
        for (int k = 0; k < 4; ++k) {
#pragma unroll
            for (int t = 0; t < 4; ++t) {
                uint32_t* bc = b[t & 1];
                uint32_t* bn = b[(t + 1) & 1];
                // prefetch the next b fragment before issuing this t's MMAs
                if (t < 3)          ldb(bn, k, t + 1);
                else if (k < 3)     ldb(bn, k + 1, 0);
                mma_bf16(acc[0][2 * t],     a[0], bc[0], bc[1]);
                mma_bf16(acc[0][2 * t + 1], a[0], bc[2], bc[3]);
                mma_bf16(acc[1][2 * t],     a[1], bc[0], bc[1]);
                mma_bf16(acc[1][2 * t + 1], a[1], bc[2], bc[3]);
                mma_bf16(acc[2][2 * t],     a[2], bc[0], bc[1]);
                mma_bf16(acc[2][2 * t + 1], a[2], bc[2], bc[3]);
                mma_bf16(acc[3][2 * t],     a[3], bc[0], bc[1]);
                mma_bf16(acc[3][2 * t + 1], a[3], bc[2], bc[3]);
            }
            if (k < 3) lda(k + 1);   // covered by the in-flight MMAs of t=3
        }
    };

    // ---- pipelined mainloop: 4 stages, w prefetched 3 chunks deep ----
    load_x(0);
    cpasync_w(0, 0);      cp_commit();
    cpasync_w(1, KC);     cp_commit();
    cpasync_w(2, 2 * KC); cp_commit();
    for (int c = 0; c < NCHUNK; ++c) {
        const int s = c & (NSTAGES - 1);
        cp_wait2();                       // w chunk c resident
        sts_x(s);
        __syncthreads();                  // stage s fully built; compute(c-1) done
        if (c + 3 < NCHUNK) cpasync_w((c + 3) & (NSTAGES - 1), (c + 3) * KC);
        cp_commit();                      // always commit (possibly empty group)
        if (c + 1 < NCHUNK) load_x((c + 1) * KC);
        compute(s);
    }

    // ---- epilogue: scores -> smem, argmax, cooperative exact rescore ----
    __syncthreads();
    float* sc = reinterpret_cast<float*>(smem);
#pragma unroll
    for (int mi = 0; mi < 4; ++mi)
#pragma unroll
        for (int nj = 0; nj < 8; ++nj) {
            const int r  = wm * 64 + mi * 16 + (lane >> 2);
            const int cc = wn * 64 + nj * 8 + ((lane & 3) << 1);
            sc[r * SC_STRIDE + cc]           = acc[mi][nj][0];
            sc[r * SC_STRIDE + cc + 1]       = acc[mi][nj][1];
            sc[(r + 8) * SC_STRIDE + cc]     = acc[mi][nj][2];
            sc[(r + 8) * SC_STRIDE + cc + 1] = acc[mi][nj][3];
        }
    __syncthreads();

    // Phase 1: per-token scan; clear winners written directly, near-ties queued.
    if (wid < 4) {
        const int r = wid * 32 + lane;
        const int t = t0 + r;
        float m1 = -__int_as_float(0x7f800000);
        float m2 = m1;
        int i1 = 0;
        for (int j = 0; j < NEXP; ++j) {
            const float v = sc[r * SC_STRIDE + j];
            if (v > m1) { m2 = m1; m1 = v; i1 = j; }
            else if (v > m2) { m2 = v; }
        }
        out[t] = 1.0f;
        if (m1 - m2 >= TAU) {
            out[T_TOK + t] = (float)i1;
        } else {
            const int p = atomicAdd(&s_cnt, 1);
            s_list[p] = r;
            s_m1[p]   = m1;
        }
    }
    __syncthreads();

    // Phase 2: warp-cooperative exact fp32 rescore of queued tokens.
    const int cnt = s_cnt;
    for (int q = wid; q < cnt; q += NTHREADS / 32) {
        const int r  = s_list[q];
        const float m1 = s_m1[q];
        const int t  = t0 + r;
        float best = -__int_as_float(0x7f800000);
        int   bi   = 0;
        const float4* xa = reinterpret_cast<const float4*>(x + (size_t)t * DIM);
        for (int e0 = 0; e0 < NEXP; e0 += 32) {
            const bool cand = sc[r * SC_STRIDE + e0 + lane] >= m1 - TAU;
            unsigned msk = __ballot_sync(0xffffffffu, cand);
            while (msk) {
                const int e = e0 + (__ffs(msk) - 1);
                msk &= msk - 1;
                const float4* wb = reinterpret_cast<const float4*>(w + (size_t)e * DIM);
                float s0 = 0.f, s1 = 0.f, s2 = 0.f, s3 = 0.f;
                for (int k = lane; k < DIM / 4; k += 32) {
                    float4 va = xa[k], vb = wb[k];
                    s0 = fmaf(va.x, vb.x, s0);
                    s1 = fmaf(va.y, vb.y, s1);
                    s2 = fmaf(va.z, vb.z, s2);
                    s3 = fmaf(va.w, vb.w, s3);
                }
                float ssum = (s0 + s1) + (s2 + s3);
#pragma unroll
                for (int off = 16; off > 0; off >>= 1)
                    ssum += __shfl_xor_sync(0xffffffffu, ssum, off);
                if (ssum > best) { best = ssum; bi = e; }
            }
        }
        if (lane == 0) out[T_TOK + t] = (float)bi;
    }
}

extern "C" void kernel_launch(void* const* d_in, const int* in_sizes, int n_in,
                              void* d_out, int out_size) {
    const float* x = (const float*)d_in[0];   // [16384, 4096] f32
    const float* w = (const float*)d_in[1];   // [256, 4096]  f32
    (void)in_sizes; (void)n_in; (void)out_size;

    cudaFuncSetAttribute(gate_mma_kernel,
                         cudaFuncAttributeMaxDynamicSharedMemorySize, SMEM_TOTAL);

    wconv_kernel<<<256, 256>>>(w);
    gate_mma_kernel<<<T_TOK / BM, NTHREADS, SMEM_TOTAL>>>(x, w, (float*)d_out);
}

// round 13
// speedup vs baseline: 1.1134x; 1.1134x over previous
#include <cuda_runtime.h>
#include <cuda_bf16.h>
#include <cstdint>

// Gate_8108898255611 — router gate, single-chain bf16 mma.sync + exact rescore.
//   out[0:T)  = 1.0f (STE forward == one-hot)
//   out[T:2T) = argmax_e <x_t, w_e> as float
// R13: BM=64, 128 threads (4 warps of the SAME 64x64 tile as R11), 2 smem
// stages (80KB) -> 2 CTAs/SM. Cross-CTA overlap hides each CTA's load/barrier
// phase behind the other's MMA phase (the mechanism R8-R10 couldn't provide
// intra-CTA). Per-SM LDSM/MMA/LDG totals unchanged vs R11.

constexpr int T_TOK = 16384;
constexpr int DIM   = 4096;
constexpr int NEXP  = 256;
constexpr int BM    = 64;             // tokens per CTA
constexpr int KC    = 64;             // k per chunk (128B bf16 rows)
constexpr int NCHUNK = DIM / KC;      // 64
constexpr int NSTAGES = 2;
constexpr int NTHREADS = 128;         // 4 warps, 1x4 grid of 64x64 tiles
constexpr float TAU = 0.02f;

constexpr int A_SZ  = BM * 128;       // 8KB  (64 rows x 128B bf16)
constexpr int B_SZ  = NEXP * 128;     // 32KB
constexpr int STAGE = A_SZ + B_SZ;    // 40KB
constexpr int SMEM_TOTAL = NSTAGES * STAGE;   // 80KB -> 2 CTAs/SM
constexpr int SC_STRIDE = 257;

__device__ __nv_bfloat16 g_w_bf[NEXP * DIM];

// ---------------- helpers ----------------
__device__ __forceinline__ uint32_t smem_u32(const void* p) {
    uint32_t a;
    asm("{ .reg .u64 t; cvta.to.shared.u64 t, %1; cvt.u32.u64 %0, t; }"
        : "=r"(a) : "l"(p));
    return a;
}
__device__ __forceinline__ uint32_t sw128(uint32_t off) {
    return off ^ ((off >> 3) & 0x70);
}
__device__ __forceinline__ uint32_t pack_bf2(__nv_bfloat16 a, __nv_bfloat16 b) {
    return (uint32_t)__bfloat16_as_ushort(a) | ((uint32_t)__bfloat16_as_ushort(b) << 16);
}
__device__ __forceinline__ void ldsm4(uint32_t* r, uint32_t addr) {
    asm("ldmatrix.sync.aligned.m8n8.x4.shared.b16 {%0,%1,%2,%3}, [%4];"
        : "=r"(r[0]), "=r"(r[1]), "=r"(r[2]), "=r"(r[3]) : "r"(addr) : "memory");
}
__device__ __forceinline__ void mma_bf16(float* d, const uint32_t* a,
                                         uint32_t b0, uint32_t b1) {
    asm("mma.sync.aligned.m16n8k16.row.col.f32.bf16.bf16.f32 "
        "{%0,%1,%2,%3}, {%4,%5,%6,%7}, {%8,%9}, {%0,%1,%2,%3};"
        : "+f"(d[0]), "+f"(d[1]), "+f"(d[2]), "+f"(d[3])
        : "r"(a[0]), "r"(a[1]), "r"(a[2]), "r"(a[3]), "r"(b0), "r"(b1));
}
__device__ __forceinline__ void cp_async16(uint32_t dst, const void* src) {
    asm volatile("cp.async.cg.shared.global [%0], [%1], 16;"
                 :: "r"(dst), "l"(src) : "memory");
}
__device__ __forceinline__ void cp_commit() {
    asm volatile("cp.async.commit_group;" ::: "memory");
}
__device__ __forceinline__ void cp_wait_all() {
    asm volatile("cp.async.wait_group 0;" ::: "memory");
}

// ---------------- w pre-convert (round-nearest bf16) ----------------
__global__ void wconv_kernel(const float* __restrict__ w) {
    int n4 = NEXP * DIM / 4;
    for (int i = blockIdx.x * blockDim.x + threadIdx.x; i < n4;
         i += gridDim.x * blockDim.x) {
        float4 v = reinterpret_cast<const float4*>(w)[i];
        reinterpret_cast<uint2*>(g_w_bf)[i] =
            make_uint2(pack_bf2(__float2bfloat16(v.x), __float2bfloat16(v.y)),
                       pack_bf2(__float2bfloat16(v.z), __float2bfloat16(v.w)));
    }
}

// ---------------- main kernel ----------------
__global__ __launch_bounds__(NTHREADS, 2)
void gate_mma_kernel(const float* __restrict__ x,
                     const float* __restrict__ w,
                     float* __restrict__ out)
{
    extern __shared__ char smem[];
    __shared__ int   s_cnt;
    __shared__ int   s_list[BM];
    __shared__ float s_m1[BM];
    const uint32_t sb = smem_u32(smem);
    const int tid  = threadIdx.x;
    const int lane = tid & 31;
    const int wid  = tid >> 5;
    const int wn   = wid;        // 0..3 -> 64-col strip (wm == 0 always)
    const int t0   = blockIdx.x * BM;
    const float* xbase = x + (size_t)t0 * DIM;

    if (tid == 0) s_cnt = 0;

    float acc[4][8][4];   // 64x64 tile: mi 0..3 (16-row), nj 0..7 (8-col)
#pragma unroll
    for (int i = 0; i < 4; i++)
#pragma unroll
        for (int j = 0; j < 8; j++)
#pragma unroll
            for (int q = 0; q < 4; q++) acc[i][j][q] = 0.f;

    float4 xv[8];  // prefetched x chunk (fp32): 64x64 f32 / 128 thr = 8 float4

    auto load_x = [&](int k0) {
#pragma unroll
        for (int t = 0; t < 8; ++t) {
            const int i = tid + t * NTHREADS;
            const int r = i >> 4, c4 = (i & 15) << 2;
            xv[t] = *reinterpret_cast<const float4*>(xbase + (size_t)r * DIM + k0 + c4);
        }
    };
    auto sts_x = [&](int s) {
        char* aB = smem + s * STAGE;
#pragma unroll
        for (int t = 0; t < 8; ++t) {
            const int i = tid + t * NTHREADS;
            const int r = i >> 4, c4 = (i & 15) << 2;
            const float4 v = xv[t];
            const uint32_t off = sw128((uint32_t)(r * 128 + c4 * 2));
            *reinterpret_cast<uint2*>(aB + off) =
                make_uint2(pack_bf2(__float2bfloat16(v.x), __float2bfloat16(v.y)),
                           pack_bf2(__float2bfloat16(v.z), __float2bfloat16(v.w)));
        }
    };
    auto cpasync_w = [&](int s, int k0) {
        const uint32_t bB = sb + s * STAGE + A_SZ;
#pragma unroll
        for (int t = 0; t < 16; ++t) {
            const int i = tid + t * NTHREADS;
            const int r = i >> 3, c16 = (i & 7) << 4;
            const uint32_t off = sw128((uint32_t)(r * 128 + c16));
            const size_t gs = ((size_t)r * DIM + k0) * 2 + c16;
            cp_async16(bB + off, (const char*)g_w_bf + gs);
        }
    };
    auto compute = [&](int s) {
        const uint32_t aB = sb + s * STAGE;
        const uint32_t bB = aB + A_SZ;
#pragma unroll
        for (int k = 0; k < 4; ++k) {
            const int kb = k * 32;
            uint32_t a[4][4];
#pragma unroll
            for (int mi = 0; mi < 4; ++mi) {
                const int row = mi * 16 + (lane & 15);
                const int byt = ((lane >> 4) << 4) + kb;
                ldsm4(a[mi], aB + sw128((uint32_t)(row * 128 + byt)));
            }
#pragma unroll
            for (int t = 0; t < 4; ++t) {
                const int nrow = wn * 64 + t * 16 + (lane & 7) + ((lane >> 4) << 3);
                const int byt  = kb + (((lane >> 3) & 1) << 4);
                uint32_t b[4];
                ldsm4(b, bB + sw128((uint32_t)(nrow * 128 + byt)));
                mma_bf16(acc[0][2 * t],     a[0], b[0], b[1]);
                mma_bf16(acc[0][2 * t + 1], a[0], b[2], b[3]);
                mma_bf16(acc[1][2 * t],     a[1], b[0], b[1]);
                mma_bf16(acc[1][2 * t + 1], a[1], b[2], b[3]);
                mma_bf16(acc[2][2 * t],     a[2], b[0], b[1]);
                mma_bf16(acc[2][2 * t + 1], a[2], b[2], b[3]);
                mma_bf16(acc[3][2 * t],     a[3], b[0], b[1]);
                mma_bf16(acc[3][2 * t + 1], a[3], b[2], b[3]);
            }
        }
    };

    // ---- mainloop: 2 stages, 1-chunk cp.async runahead ----
    // Cross-CTA overlap (2 CTAs/SM) hides the serial load phase.
    // WAR: cp into stage s^1 (= chunk c-1's stage) is issued after bar(c),
    // which all warps pass only after finishing compute(c-1).
    load_x(0);
    cpasync_w(0, 0);
    cp_commit();
    for (int c = 0; c < NCHUNK; ++c) {
        const int s = c & 1;
        cp_wait_all();                    // w chunk c resident
        sts_x(s);
        __syncthreads();                  // stage s built; compute(c-1) done
        if (c + 1 < NCHUNK) {
            cpasync_w(s ^ 1, (c + 1) * KC);
            cp_commit();
            load_x((c + 1) * KC);
        }
        compute(s);
    }

    // ---- epilogue: scores -> smem, argmax, cooperative exact rescore ----
    __syncthreads();
    float* sc = reinterpret_cast<float*>(smem);
#pragma unroll
    for (int mi = 0; mi < 4; ++mi)
#pragma unroll
        for (int nj = 0; nj < 8; ++nj) {
            const int r  = mi * 16 + (lane >> 2);
            const int cc = wn * 64 + nj * 8 + ((lane & 3) << 1);
            sc[r * SC_STRIDE + cc]           = acc[mi][nj][0];
            sc[r * SC_STRIDE + cc + 1]       = acc[mi][nj][1];
            sc[(r + 8) * SC_STRIDE + cc]     = acc[mi][nj][2];
            sc[(r + 8) * SC_STRIDE + cc + 1] = acc[mi][nj][3];
        }
    __syncthreads();

    // Phase 1: per-token scan; clear winners written directly, near-ties queued.
    if (wid < 2) {
        const int r = wid * 32 + lane;
        const int t = t0 + r;
        float m1 = -__int_as_float(0x7f800000);
        float m2 = m1;
        int i1 = 0;
        for (int j = 0; j < NEXP; ++j) {
            const float v = sc[r * SC_STRIDE + j];
            if (v > m1) { m2 = m1; m1 = v; i1 = j; }
            else if (v > m2) { m2 = v; }
        }
        out[t] = 1.0f;
        if (m1 - m2 >= TAU) {
            out[T_TOK + t] = (float)i1;
        } else {
            const int p = atomicAdd(&s_cnt, 1);
            s_list[p] = r;
            s_m1[p]   = m1;
        }
    }
    __syncthreads();

    // Phase 2: warp-cooperative exact fp32 rescore of queued tokens.
    const int cnt = s_cnt;
    for (int q = wid; q < cnt; q += NTHREADS / 32) {
        const int r  = s_list[q];
        const float m1 = s_m1[q];
        const int t  = t0 + r;
        float best = -__int_as_float(0x7f800000);
        int   bi   = 0;
        const float4* xa = reinterpret_cast<const float4*>(x + (size_t)t * DIM);
        for (int e0 = 0; e0 < NEXP; e0 += 32) {
            const bool cand = sc[r * SC_STRIDE + e0 + lane] >= m1 - TAU;
            unsigned msk = __ballot_sync(0xffffffffu, cand);
            while (msk) {
                const int e = e0 + (__ffs(msk) - 1);
                msk &= msk - 1;
                const float4* wb = reinterpret_cast<const float4*>(w + (size_t)e * DIM);
                float s0 = 0.f, s1 = 0.f, s2 = 0.f, s3 = 0.f;
                for (int k = lane; k < DIM / 4; k += 32) {
                    float4 va = xa[k], vb = wb[k];
                    s0 = fmaf(va.x, vb.x, s0);
                    s1 = fmaf(va.y, vb.y, s1);
                    s2 = fmaf(va.z, vb.z, s2);
                    s3 = fmaf(va.w, vb.w, s3);
                }
                float ssum = (s0 + s1) + (s2 + s3);
#pragma unroll
                for (int off = 16; off > 0; off >>= 1)
                    ssum += __shfl_xor_sync(0xffffffffu, ssum, off);
                if (ssum > best) { best = ssum; bi = e; }
            }
        }
        if (lane == 0) out[T_TOK + t] = (float)bi;
    }
}

extern "C" void kernel_launch(void* const* d_in, const int* in_sizes, int n_in,
                              void* d_out, int out_size) {
    const float* x = (const float*)d_in[0];   // [16384, 4096] f32
    const float* w = (const float*)d_in[1];   // [256, 4096]  f32
    (void)in_sizes; (void)n_in; (void)out_size;

    cudaFuncSetAttribute(gate_mma_kernel,
                         cudaFuncAttributeMaxDynamicSharedMemorySize, SMEM_TOTAL);

    wconv_kernel<<<256, 256>>>(w);
    gate_mma_kernel<<<T_TOK / BM, NTHREADS, SMEM_TOTAL>>>(x, w, (float*)d_out);
}

// round 14
// speedup vs baseline: 1.3157x; 1.1817x over previous
#include <cuda_runtime.h>
#include <cuda_bf16.h>
#include <cstdint>

// Gate_8108898255611 — router gate, single-chain bf16 mma.sync + exact rescore.
//   out[0:T)  = 1.0f (STE forward == one-hot)
//   out[T:2T) = argmax_e <x_t, w_e> as float
// R14: R11 (best: 146us, 8 warps, 64x64 tiles, 4 stages) with the producer
// work (LDG x / STS x / cp.async w) interleaved INTO the k-blocks of the
// previous chunk's MMA phase. Removes the serial load phase between barriers
// that kept the tensor pipe dark ~55% of each chunk. Zero extra registers.

constexpr int T_TOK = 16384;
constexpr int DIM   = 4096;
constexpr int NEXP  = 256;
constexpr int BM    = 128;            // tokens per CTA
constexpr int KC    = 64;             // k per chunk (128B bf16 rows)
constexpr int NCHUNK = DIM / KC;      // 64
constexpr int NSTAGES = 4;
constexpr int NTHREADS = 256;         // 8 warps, 2x4 grid of 64x64 tiles
constexpr float TAU = 0.02f;

constexpr int A_SZ  = BM * 128;       // 16KB (128 rows x 128B bf16)
constexpr int B_SZ  = NEXP * 128;     // 32KB
constexpr int STAGE = A_SZ + B_SZ;    // 48KB
constexpr int SMEM_TOTAL = NSTAGES * STAGE;   // 192KB
constexpr int SC_STRIDE = 257;

__device__ __nv_bfloat16 g_w_bf[NEXP * DIM];

// ---------------- helpers ----------------
__device__ __forceinline__ uint32_t smem_u32(const void* p) {
    uint32_t a;
    asm("{ .reg .u64 t; cvta.to.shared.u64 t, %1; cvt.u32.u64 %0, t; }"
        : "=r"(a) : "l"(p));
    return a;
}
__device__ __forceinline__ uint32_t sw128(uint32_t off) {
    return off ^ ((off >> 3) & 0x70);
}
__device__ __forceinline__ uint32_t pack_bf2(__nv_bfloat16 a, __nv_bfloat16 b) {
    return (uint32_t)__bfloat16_as_ushort(a) | ((uint32_t)__bfloat16_as_ushort(b) << 16);
}
__device__ __forceinline__ void ldsm4(uint32_t* r, uint32_t addr) {
    asm("ldmatrix.sync.aligned.m8n8.x4.shared.b16 {%0,%1,%2,%3}, [%4];"
        : "=r"(r[0]), "=r"(r[1]), "=r"(r[2]), "=r"(r[3]) : "r"(addr) : "memory");
}
__device__ __forceinline__ void mma_bf16(float* d, const uint32_t* a,
                                         uint32_t b0, uint32_t b1) {
    asm("mma.sync.aligned.m16n8k16.row.col.f32.bf16.bf16.f32 "
        "{%0,%1,%2,%3}, {%4,%5,%6,%7}, {%8,%9}, {%0,%1,%2,%3};"
        : "+f"(d[0]), "+f"(d[1]), "+f"(d[2]), "+f"(d[3])
        : "r"(a[0]), "r"(a[1]), "r"(a[2]), "r"(a[3]), "r"(b0), "r"(b1));
}
__device__ __forceinline__ void cp_async16(uint32_t dst, const void* src) {
    asm volatile("cp.async.cg.shared.global [%0], [%1], 16;"
                 :: "r"(dst), "l"(src) : "memory");
}
__device__ __forceinline__ void cp_commit() {
    asm volatile("cp.async.commit_group;" ::: "memory");
}
__device__ __forceinline__ void cp_wait2() {
    asm volatile("cp.async.wait_group 2;" ::: "memory");
}

// ---------------- w pre-convert (round-nearest bf16) ----------------
__global__ void wconv_kernel(const float* __restrict__ w) {
    int n4 = NEXP * DIM / 4;
    for (int i = blockIdx.x * blockDim.x + threadIdx.x; i < n4;
         i += gridDim.x * blockDim.x) {
        float4 v = reinterpret_cast<const float4*>(w)[i];
        reinterpret_cast<uint2*>(g_w_bf)[i] =
            make_uint2(pack_bf2(__float2bfloat16(v.x), __float2bfloat16(v.y)),
                       pack_bf2(__float2bfloat16(v.z), __float2bfloat16(v.w)));
    }
}

// ---------------- main kernel ----------------
__global__ __launch_bounds__(NTHREADS, 1)
void gate_mma_kernel(const float* __restrict__ x,
                     const float* __restrict__ w,
                     float* __restrict__ out)
{
    extern __shared__ char smem[];
    __shared__ int   s_cnt;
    __shared__ int   s_list[BM];
    __shared__ float s_m1[BM];
    const uint32_t sb = smem_u32(smem);
    const int tid  = threadIdx.x;
    const int lane = tid & 31;
    const int wid  = tid >> 5;
    const int wm   = wid >> 2;   // 0..1 -> 64-row strip
    const int wn   = wid & 3;    // 0..3 -> 64-col strip
    const int t0   = blockIdx.x * BM;
    const float* xbase = x + (size_t)t0 * DIM;

    if (tid == 0) s_cnt = 0;

    float acc[4][8][4];   // 64x64 tile: mi 0..3 (16-row), nj 0..7 (8-col)
#pragma unroll
    for (int i = 0; i < 4; i++)
#pragma unroll
        for (int j = 0; j < 8; j++)
#pragma unroll
            for (int q = 0; q < 4; q++) acc[i][j][q] = 0.f;

    float4 xv[8];  // prefetched x chunk (fp32), live across compute (as in R11)

    auto load_x = [&](int k0) {
#pragma unroll
        for (int t = 0; t < 8; ++t) {
            const int i = tid + t * NTHREADS;
            const int r = i >> 4, c4 = (i & 15) << 2;
            xv[t] = *reinterpret_cast<const float4*>(xbase + (size_t)r * DIM + k0 + c4);
        }
    };
    auto sts_x = [&](int s) {
        char* aB = smem + s * STAGE;
#pragma unroll
        for (int t = 0; t < 8; ++t) {
            const int i = tid + t * NTHREADS;
            const int r = i >> 4, c4 = (i & 15) << 2;
            const float4 v = xv[t];
            const uint32_t off = sw128((uint32_t)(r * 128 + c4 * 2));
            *reinterpret_cast<uint2*>(aB + off) =
                make_uint2(pack_bf2(__float2bfloat16(v.x), __float2bfloat16(v.y)),
                           pack_bf2(__float2bfloat16(v.z), __float2bfloat16(v.w)));
        }
    };
    auto cpasync_w = [&](int s, int k0) {
        const uint32_t bB = sb + s * STAGE + A_SZ;
#pragma unroll
        for (int t = 0; t < 8; ++t) {
            const int i = tid + t * NTHREADS;
            const int r = i >> 3, c16 = (i & 7) << 4;
            const uint32_t off = sw128((uint32_t)(r * 128 + c16));
            const size_t gs = ((size_t)r * DIM + k0) * 2 + c16;
            cp_async16(bB + off, (const char*)g_w_bf + gs);
        }
    };

    // ---- prologue: x for stage 0; w for chunks 0,1,2 (groups 1..3) ----
    load_x(0);
    sts_x(0);
    cpasync_w(0, 0);      cp_commit();
    cpasync_w(1, KC);     cp_commit();
    cpasync_w(2, 2 * KC); cp_commit();

    // ---- mainloop: producer work interleaved into the k-blocks ----
    // top of iter c: 3+c groups committed, wait 2 -> w chunks 0..c resident.
    // A(stage (c+1)&3) written during iter c (k==3 hook), read after next bar.
    // WAR: stage (c+1)&3 last read at compute(c-3); stage (c+3)&3 B last read
    // at compute(c-1); both strictly before this iteration's writes.
    for (int c = 0; c < NCHUNK; ++c) {
        const int s = c & (NSTAGES - 1);
        cp_wait2();
        __syncthreads();
        const uint32_t aB = sb + s * STAGE;
        const uint32_t bB = aB + A_SZ;
#pragma unroll
        for (int k = 0; k < 4; ++k) {
            // producer hooks, hidden under this k-block's MMA stream
            if (k == 0 && c + 1 < NCHUNK) load_x((c + 1) * KC);
            if (k == 1) {
                if (c + 3 < NCHUNK) cpasync_w((c + 3) & (NSTAGES - 1), (c + 3) * KC);
                cp_commit();   // exactly one commit per iteration (may be empty)
            }
            if (k == 3 && c + 1 < NCHUNK) sts_x((c + 1) & (NSTAGES - 1));

            const int kb = k * 32;
            uint32_t a[4][4];
#pragma unroll
            for (int mi = 0; mi < 4; ++mi) {
                const int row = wm * 64 + mi * 16 + (lane & 15);
                const int byt = ((lane >> 4) << 4) + kb;
                ldsm4(a[mi], aB + sw128((uint32_t)(row * 128 + byt)));
            }
#pragma unroll
            for (int t = 0; t < 4; ++t) {
                const int nrow = wn * 64 + t * 16 + (lane & 7) + ((lane >> 4) << 3);
                const int byt  = kb + (((lane >> 3) & 1) << 4);
                uint32_t b[4];
                ldsm4(b, bB + sw128((uint32_t)(nrow * 128 + byt)));
                mma_bf16(acc[0][2 * t],     a[0], b[0], b[1]);
                mma_bf16(acc[0][2 * t + 1], a[0], b[2], b[3]);
                mma_bf16(acc[1][2 * t],     a[1], b[0], b[1]);
                mma_bf16(acc[1][2 * t + 1], a[1], b[2], b[3]);
                mma_bf16(acc[2][2 * t],     a[2], b[0], b[1]);
                mma_bf16(acc[2][2 * t + 1], a[2], b[2], b[3]);
                mma_bf16(acc[3][2 * t],     a[3], b[0], b[1]);
                mma_bf16(acc[3][2 * t + 1], a[3], b[2], b[3]);
            }
        }
    }

    // ---- epilogue: scores -> smem, argmax, cooperative exact rescore ----
    __syncthreads();
    float* sc = reinterpret_cast<float*>(smem);
#pragma unroll
    for (int mi = 0; mi < 4; ++mi)
#pragma unroll
        for (int nj = 0; nj < 8; ++nj) {
            const int r  = wm * 64 + mi * 16 + (lane >> 2);
            const int cc = wn * 64 + nj * 8 + ((lane & 3) << 1);
            sc[r * SC_STRIDE + cc]           = acc[mi][nj][0];
            sc[r * SC_STRIDE + cc + 1]       = acc[mi][nj][1];
            sc[(r + 8) * SC_STRIDE + cc]     = acc[mi][nj][2];
            sc[(r + 8) * SC_STRIDE + cc + 1] = acc[mi][nj][3];
        }
    __syncthreads();

    // Phase 1: per-token scan; clear winners written directly, near-ties queued.
    if (wid < 4) {
        const int r = wid * 32 + lane;
        const int t = t0 + r;
        float m1 = -__int_as_float(0x7f800000);
        float m2 = m1;
        int i1 = 0;
        for (int j = 0; j < NEXP; ++j) {
            const float v = sc[r * SC_STRIDE + j];
            if (v > m1) { m2 = m1; m1 = v; i1 = j; }
            else if (v > m2) { m2 = v; }
        }
        out[t] = 1.0f;
        if (m1 - m2 >= TAU) {
            out[T_TOK + t] = (float)i1;
        } else {
            const int p = atomicAdd(&s_cnt, 1);
            s_list[p] = r;
            s_m1[p]   = m1;
        }
    }
    __syncthreads();

    // Phase 2: warp-cooperative exact fp32 rescore of queued tokens.
    const int cnt = s_cnt;
    for (int q = wid; q < cnt; q += NTHREADS / 32) {
        const int r  = s_list[q];
        const float m1 = s_m1[q];
        const int t  = t0 + r;
        float best = -__int_as_float(0x7f800000);
        int   bi   = 0;
        const float4* xa = reinterpret_cast<const float4*>(x + (size_t)t * DIM);
        for (int e0 = 0; e0 < NEXP; e0 += 32) {
            const bool cand = sc[r * SC_STRIDE + e0 + lane] >= m1 - TAU;
            unsigned msk = __ballot_sync(0xffffffffu, cand);
            while (msk) {
                const int e = e0 + (__ffs(msk) - 1);
                msk &= msk - 1;
                const float4* wb = reinterpret_cast<const float4*>(w + (size_t)e * DIM);
                float s0 = 0.f, s1 = 0.f, s2 = 0.f, s3 = 0.f;
                for (int k = lane; k < DIM / 4; k += 32) {
                    float4 va = xa[k], vb = wb[k];
                    s0 = fmaf(va.x, vb.x, s0);
                    s1 = fmaf(va.y, vb.y, s1);
                    s2 = fmaf(va.z, vb.z, s2);
                    s3 = fmaf(va.w, vb.w, s3);
                }
                float ssum = (s0 + s1) + (s2 + s3);
#pragma unroll
                for (int off = 16; off > 0; off >>= 1)
                    ssum += __shfl_xor_sync(0xffffffffu, ssum, off);
                if (ssum > best) { best = ssum; bi = e; }
            }
        }
        if (lane == 0) out[T_TOK + t] = (float)bi;
    }
}

extern "C" void kernel_launch(void* const* d_in, const int* in_sizes, int n_in,
                              void* d_out, int out_size) {
    const float* x = (const float*)d_in[0];   // [16384, 4096] f32
    const float* w = (const float*)d_in[1];   // [256, 4096]  f32
    (void)in_sizes; (void)n_in; (void)out_size;

    cudaFuncSetAttribute(gate_mma_kernel,
                         cudaFuncAttributeMaxDynamicSharedMemorySize, SMEM_TOTAL);

    wconv_kernel<<<256, 256>>>(w);
    gate_mma_kernel<<<T_TOK / BM, NTHREADS, SMEM_TOTAL>>>(x, w, (float*)d_out);
}